// round 14
// baseline (speedup 1.0000x reference)
#include <cuda_runtime.h>
#include <cuda_bf16.h>
#include <cuda_fp16.h>
#include <stdint.h>

// GCN graph classifier: 2x (GCNConv + ReLU) -> global_mean_pool -> Linear
// N=100k, E=1.6M, H=128, G=512, OUT=2.
//
// R14 vs R13 (249.0us):
//  - pooling pass deleted: agg2 projects each node's relu'd features to the
//    2 classifier logits in-register (lane-wise dot with Wl + warp shuffle)
//    and accumulates into per-graph fixed-point integer atomics (2^20 scale,
//    order-independent => deterministic). Gather grid shape unchanged.
//  - tiny k_final (1 block): divide by graph node count (binary search on
//    sorted batch) + bias. g_pool zeroed by prep1 each invocation.
//  - everything else as R13: packed 64-bit degree atomics, single-pass
//    lookback scan, split-bf16 TC GEMMs, fp16 intermediates, CSR||GEMM1 fork.

#define HD   128
#define NMAX 100352
#define EMAX 1605632
#define WPAD 136          // padded k-stride (bf16 elems) for smem tiles
#define GPMAX 2048        // pooled logits capacity (2*G, G<=1024)

__device__ __align__(16) unsigned long long g_degcnt[NMAX]; // zero-init; reset by scan
__device__ __align__(16) float g_dis[NMAX];
__device__ __align__(16) int   g_row[EMAX];
__device__ __align__(16) int   g_col[EMAX];
__device__ __align__(16) int   g_batch[NMAX];
__device__ __align__(16) int   g_off[NMAX + 1];
__device__ __align__(16) int   g_cur[NMAX];
__device__ __align__(16) int   g_bsum[128];          // lookback aggregates+flag
__device__ __align__(16) unsigned long long g_pool[GPMAX]; // fixed-point logits
__device__ __align__(16) int2  g_edge[EMAX];         // {src row, coef bits}
__device__ __align__(16) __half g_xwh[(size_t)NMAX * HD];  // GEMM1 out (fp16)
__device__ __align__(16) __half g_xwh2[(size_t)NMAX * HD]; // GEMM2 out (fp16)
__device__ __align__(16) __half g_hh[(size_t)NMAX * HD];   // agg1 out (fp16)
__device__ __align__(16) __nv_bfloat16 g_Wh[2][HD * HD];   // W^T hi, [n][k]
__device__ __align__(16) __nv_bfloat16 g_Wl[2][HD * HD];   // W^T lo

#define POOL_SCALE 1048576.0f      // 2^20
#define POOL_INV   (1.0f / 1048576.0f)

// ---------------------------------------------------------------------------
// dtype detection (int64 arrays have zero hi-words at odd 32-bit indices)
// ---------------------------------------------------------------------------
__device__ __forceinline__ int detect_ei64(const int* ei32)
{
    int lane = threadIdx.x & 31;
    int v = ei32[2 * lane + 1];
    return __all_sync(0xffffffffu, v == 0);
}

__device__ __forceinline__ int detect_b64(const int* b32, int n)
{
    int lane = threadIdx.x & 31;
    int base = (n > 64) ? ((n - 64) & ~1) : 0;
    int v = b32[base + 2 * lane + 1];
    return __all_sync(0xffffffffu, v == 0);
}

// ---------------------------------------------------------------------------
// prep1: convert edge_index + batch; ONE packed 64-bit atomic per edge.
// block 0 clears lookback flags; block 1 clears pooled-logit accumulators.
// ---------------------------------------------------------------------------
__global__ void k_prep1(const void* __restrict__ ei, const void* __restrict__ bt,
                        const float* __restrict__ ew, int n, int e)
{
    __shared__ int s_ei64, s_b64;
    const int* ei32 = (const int*)ei;
    const int* bt32 = (const int*)bt;
    int tid = threadIdx.x;
    if (tid < 32) {
        int r = detect_ei64(ei32);
        if (tid == 0) s_ei64 = r;
    } else if (tid < 64) {
        int r = detect_b64(bt32, n);
        if (tid == 32) s_b64 = r;
    }
    if (blockIdx.x == 0 && tid < 128)
        g_bsum[tid] = 0;                 // clear lookback flags
    if (blockIdx.x == 1) {
#pragma unroll
        for (int k = 0; k < GPMAX / 256; k++)
            g_pool[tid + k * 256] = 0ULL;
    }
    __syncthreads();

    int i = blockIdx.x * blockDim.x + tid;
    if (i < e) {
        int r, c;
        if (s_ei64) {
            const long long* p = (const long long*)ei;
            r = (int)p[i];
            c = (int)p[(size_t)e + i];
        } else {
            r = ei32[i];
            c = ei32[e + i];
        }
        g_row[i] = r;
        g_col[i] = c;
        unsigned fx = __float2uint_rn(ew[i] * 16777216.0f);   // ew * 2^24
        atomicAdd(&g_degcnt[c], (1ULL << 32) | (unsigned long long)fx);
    }
    if (i < n)
        g_batch[i] = s_b64 ? (int)((const long long*)bt)[i] : bt32[i];
}

// ---------------------------------------------------------------------------
// fused single-pass scan (decoupled lookback) + dis; resets g_degcnt.
// ---------------------------------------------------------------------------
__global__ void k_scan_all(int n, int e)
{
    __shared__ int s[1024];
    __shared__ int sbase;
    int b = blockIdx.x;
    int tid = threadIdx.x;
    int i = b * 1024 + tid;

    unsigned long long packed = 0;
    if (i < n) packed = g_degcnt[i];
    int v0 = (int)(packed >> 32);
    if (i < n) {
        float deg = (float)(unsigned)(packed & 0xffffffffu) * (1.0f / 16777216.0f);
        g_dis[i] = rsqrtf(deg + 1.0f);   // +1 = self-loop
        g_degcnt[i] = 0ULL;              // reset for next invocation
    }

    s[tid] = v0;
    __syncthreads();
    for (int off = 1; off < 1024; off <<= 1) {
        int t = 0;
        if (tid >= off) t = s[tid - off];
        __syncthreads();
        if (tid >= off) s[tid] += t;
        __syncthreads();
    }
    if (tid == 0) {
        sbase = 0;
        atomicExch(&g_bsum[b], (int)(0x80000000u | (unsigned)s[1023]));
    }
    __syncthreads();
    if (tid < b) {
        unsigned v;
        do {
            v = (unsigned)atomicAdd(&g_bsum[tid], 0);
        } while (!(v & 0x80000000u));
        atomicAdd(&sbase, (int)(v & 0x7fffffffu));
    }
    __syncthreads();
    if (i < n) {
        int ex = sbase + s[tid] - v0;   // exclusive prefix
        g_off[i] = ex;
        g_cur[i] = ex;
    }
    if (b == 0 && tid == 0) g_off[n] = e;
}

__global__ void k_scatter(const float* __restrict__ ew, int e)
{
    int i = blockIdx.x * blockDim.x + threadIdx.x;
    if (i >= e) return;
    int r = g_row[i];
    int c = g_col[i];
    float coef = g_dis[r] * ew[i] * g_dis[c];
    int slot = atomicAdd(&g_cur[c], 1);
    g_edge[slot] = make_int2(r, __float_as_int(coef));
}

// ---------------------------------------------------------------------------
// W split: W[k][n] fp32 -> transposed bf16 hi/lo [n][k]
// ---------------------------------------------------------------------------
__global__ void k_wsplit(const float* __restrict__ W1, const float* __restrict__ W2)
{
    int idx = blockIdx.x * blockDim.x + threadIdx.x;
    if (idx >= HD * HD) return;
    int k = idx >> 7, nn = idx & 127;
    float w1 = W1[idx], w2 = W2[idx];
    __nv_bfloat16 h1 = __float2bfloat16(w1);
    __nv_bfloat16 h2 = __float2bfloat16(w2);
    int o = nn * HD + k;
    g_Wh[0][o] = h1;
    g_Wl[0][o] = __float2bfloat16(w1 - __bfloat162float(h1));
    g_Wh[1][o] = h2;
    g_Wl[1][o] = __float2bfloat16(w2 - __bfloat162float(h2));
}

// ---------------------------------------------------------------------------
// tensor-core GEMM: Cout[rows x 128] = A[rows x 128] @ W  (split-bf16)
// ---------------------------------------------------------------------------
#define MMA16816(d, a, b)                                                     \
    asm volatile("mma.sync.aligned.m16n8k16.row.col.f32.bf16.bf16.f32 "       \
                 "{%0,%1,%2,%3}, {%4,%5,%6,%7}, {%8,%9}, {%0,%1,%2,%3};"      \
                 : "+f"((d)[0]), "+f"((d)[1]), "+f"((d)[2]), "+f"((d)[3])     \
                 : "r"((a)[0]), "r"((a)[1]), "r"((a)[2]), "r"((a)[3]),        \
                   "r"((b)[0]), "r"((b)[1]))

__global__ void __launch_bounds__(256) k_gemm_tc(const float* __restrict__ Xin,
                                                 int widx, int useH, int n)
{
    extern __shared__ __align__(16) char smraw[];
    __nv_bfloat16* Ah = (__nv_bfloat16*)smraw;       // [128][WPAD]
    __nv_bfloat16* Al = Ah + 128 * WPAD;
    __nv_bfloat16* Bh = Al + 128 * WPAD;             // W^T [n][k], [128][WPAD]
    __nv_bfloat16* Bl = Bh + 128 * WPAD;

    __half* Cout = useH ? g_xwh2 : g_xwh;
    int tid = threadIdx.x;
    int rowBase = blockIdx.x * 128;

    // stage + split A tile
#pragma unroll
    for (int i = 0; i < 16; i++) {
        int f4 = tid + i * 256;
        int r = f4 >> 5;
        int c4 = (f4 & 31) * 4;
        int ar = min(rowBase + r, n - 1);
        float4 v;
        if (useH) {
            uint2 hv = *(const uint2*)(g_hh + (size_t)ar * HD + c4);
            float2 f01 = __half22float2(*(__half2*)&hv.x);
            float2 f23 = __half22float2(*(__half2*)&hv.y);
            v = make_float4(f01.x, f01.y, f23.x, f23.y);
        } else {
            v = *(const float4*)(Xin + (size_t)ar * HD + c4);
        }
        __nv_bfloat16 hx = __float2bfloat16(v.x);
        __nv_bfloat16 hy = __float2bfloat16(v.y);
        __nv_bfloat16 hz = __float2bfloat16(v.z);
        __nv_bfloat16 hw = __float2bfloat16(v.w);
        __nv_bfloat16 lx = __float2bfloat16(v.x - __bfloat162float(hx));
        __nv_bfloat16 ly = __float2bfloat16(v.y - __bfloat162float(hy));
        __nv_bfloat16 lz = __float2bfloat16(v.z - __bfloat162float(hz));
        __nv_bfloat16 lw = __float2bfloat16(v.w - __bfloat162float(hw));
        __nv_bfloat162 h01, h23, l01, l23;
        h01.x = hx; h01.y = hy; h23.x = hz; h23.y = hw;
        l01.x = lx; l01.y = ly; l23.x = lz; l23.y = lw;
        uint2 uh, ul;
        uh.x = *(uint32_t*)&h01; uh.y = *(uint32_t*)&h23;
        ul.x = *(uint32_t*)&l01; ul.y = *(uint32_t*)&l23;
        *(uint2*)&Ah[r * WPAD + c4] = uh;
        *(uint2*)&Al[r * WPAD + c4] = ul;
    }

    // stage W^T tiles
#pragma unroll
    for (int i = 0; i < 8; i++) {
        int idx8 = (tid + i * 256) * 8;
        int r = idx8 >> 7;
        int c = idx8 & 127;
        *(uint4*)&Bh[r * WPAD + c] = *(const uint4*)&g_Wh[widx][idx8];
        *(uint4*)&Bl[r * WPAD + c] = *(const uint4*)&g_Wl[widx][idx8];
    }
    __syncthreads();

    int lane = tid & 31;
    int w = tid >> 5;
    int g = lane >> 2;
    int t = lane & 3;
    int wm0 = (w & 1) * 64;
    int wn0 = (w >> 1) * 32;

    float acc[4][4][4];
#pragma unroll
    for (int mb = 0; mb < 4; mb++)
#pragma unroll
        for (int nb = 0; nb < 4; nb++)
#pragma unroll
            for (int q = 0; q < 4; q++) acc[mb][nb][q] = 0.0f;

#pragma unroll
    for (int ks = 0; ks < 8; ks++) {
        int k0 = ks * 16 + t * 2;
        uint32_t ah[4][4], al[4][4];
#pragma unroll
        for (int mb = 0; mb < 4; mb++) {
            int r0 = wm0 + mb * 16 + g;
            ah[mb][0] = *(const uint32_t*)&Ah[r0 * WPAD + k0];
            ah[mb][1] = *(const uint32_t*)&Ah[(r0 + 8) * WPAD + k0];
            ah[mb][2] = *(const uint32_t*)&Ah[r0 * WPAD + k0 + 8];
            ah[mb][3] = *(const uint32_t*)&Ah[(r0 + 8) * WPAD + k0 + 8];
            al[mb][0] = *(const uint32_t*)&Al[r0 * WPAD + k0];
            al[mb][1] = *(const uint32_t*)&Al[(r0 + 8) * WPAD + k0];
            al[mb][2] = *(const uint32_t*)&Al[r0 * WPAD + k0 + 8];
            al[mb][3] = *(const uint32_t*)&Al[(r0 + 8) * WPAD + k0 + 8];
        }
        uint32_t bh[4][2], bl[4][2];
#pragma unroll
        for (int nb = 0; nb < 4; nb++) {
            int nr = wn0 + nb * 8 + g;
            bh[nb][0] = *(const uint32_t*)&Bh[nr * WPAD + k0];
            bh[nb][1] = *(const uint32_t*)&Bh[nr * WPAD + k0 + 8];
            bl[nb][0] = *(const uint32_t*)&Bl[nr * WPAD + k0];
            bl[nb][1] = *(const uint32_t*)&Bl[nr * WPAD + k0 + 8];
        }
#pragma unroll
        for (int mb = 0; mb < 4; mb++)
#pragma unroll
            for (int nb = 0; nb < 4; nb++) {
                MMA16816(acc[mb][nb], ah[mb], bh[nb]);
                MMA16816(acc[mb][nb], ah[mb], bl[nb]);
                MMA16816(acc[mb][nb], al[mb], bh[nb]);
            }
    }

    // write C as fp16
#pragma unroll
    for (int mb = 0; mb < 4; mb++) {
#pragma unroll
        for (int nb = 0; nb < 4; nb++) {
            int r0 = rowBase + wm0 + mb * 16 + g;
            int c0 = wn0 + nb * 8 + t * 2;
            if (r0 < n) {
                __half2 v0 = __floats2half2_rn(acc[mb][nb][0], acc[mb][nb][1]);
                *(__half2*)&Cout[(size_t)r0 * HD + c0] = v0;
            }
            if (r0 + 8 < n) {
                __half2 v1 = __floats2half2_rn(acc[mb][nb][2], acc[mb][nb][3]);
                *(__half2*)&Cout[(size_t)(r0 + 8) * HD + c0] = v1;
            }
        }
    }
}

// ---------------------------------------------------------------------------
// aggregation: fp16 gathers, fp32 accumulate. warp per node, full grid.
// mode 0: src g_xwh,  write fp16 g_hh               (layer 1)
// mode 1: src g_xwh2, project to 2 logits with Wl and accumulate into
//         g_pool[batch[node]] via fixed-point integer atomics (layer 2)
// ---------------------------------------------------------------------------
__device__ __forceinline__ void h4_acc(float4& acc, uint2 u, float c)
{
    float2 f01 = __half22float2(*(__half2*)&u.x);
    float2 f23 = __half22float2(*(__half2*)&u.y);
    acc.x += c * f01.x;
    acc.y += c * f01.y;
    acc.z += c * f23.x;
    acc.w += c * f23.y;
}

__global__ void k_agg(const float* __restrict__ bias,
                      const float* __restrict__ Wl, int mode, int n)
{
    int gw = (blockIdx.x * blockDim.x + threadIdx.x) >> 5;
    int lane = threadIdx.x & 31;
    if (gw >= n) return;

    const uint2* x2 = (const uint2*)(mode ? g_xwh2 : g_xwh);
    float sc = g_dis[gw];
    float4 acc = make_float4(0.f, 0.f, 0.f, 0.f);
    h4_acc(acc, x2[(size_t)gw * 32 + lane], sc * sc);

    int p  = g_off[gw];
    int p1 = g_off[gw + 1];
    for (; p + 3 < p1; p += 4) {
        int2 e0 = g_edge[p];
        int2 e1 = g_edge[p + 1];
        int2 e2 = g_edge[p + 2];
        int2 e3 = g_edge[p + 3];
        uint2 u0 = x2[(size_t)e0.x * 32 + lane];
        uint2 u1 = x2[(size_t)e1.x * 32 + lane];
        uint2 u2 = x2[(size_t)e2.x * 32 + lane];
        uint2 u3 = x2[(size_t)e3.x * 32 + lane];
        h4_acc(acc, u0, __int_as_float(e0.y));
        h4_acc(acc, u1, __int_as_float(e1.y));
        h4_acc(acc, u2, __int_as_float(e2.y));
        h4_acc(acc, u3, __int_as_float(e3.y));
    }
    for (; p < p1; p++) {
        int2 e0 = g_edge[p];
        uint2 u0 = x2[(size_t)e0.x * 32 + lane];
        h4_acc(acc, u0, __int_as_float(e0.y));
    }

    float4 bb = ((const float4*)bias)[lane];
    float ox = fmaxf(acc.x + bb.x, 0.0f);
    float oy = fmaxf(acc.y + bb.y, 0.0f);
    float oz = fmaxf(acc.z + bb.z, 0.0f);
    float ow = fmaxf(acc.w + bb.w, 0.0f);

    if (mode == 0) {
        __half2 h01 = __floats2half2_rn(ox, oy);
        __half2 h23 = __floats2half2_rn(oz, ow);
        uint2 u;
        u.x = *(uint32_t*)&h01;
        u.y = *(uint32_t*)&h23;
        *(uint2*)&g_hh[(size_t)gw * HD + 4 * lane] = u;
    } else {
        // project: features 4*lane..4*lane+3 dot Wl[:,0] and Wl[:,1]
        float4 w0 = ((const float4*)Wl)[2 * lane];       // Wl[4l..4l+1][0..1]
        float4 w1 = ((const float4*)Wl)[2 * lane + 1];   // Wl[4l+2..4l+3][0..1]
        float d0 = ox * w0.x + oy * w0.z + oz * w1.x + ow * w1.z;
        float d1 = ox * w0.y + oy * w0.w + oz * w1.y + ow * w1.w;
#pragma unroll
        for (int off = 16; off > 0; off >>= 1) {
            d0 += __shfl_down_sync(0xffffffffu, d0, off);
            d1 += __shfl_down_sync(0xffffffffu, d1, off);
        }
        if (lane == 0) {
            int b = g_batch[gw];
            long long q0 = (long long)llrintf(d0 * POOL_SCALE);
            long long q1 = (long long)llrintf(d1 * POOL_SCALE);
            atomicAdd(&g_pool[b * 2 + 0], (unsigned long long)q0);
            atomicAdd(&g_pool[b * 2 + 1], (unsigned long long)q1);
        }
    }
}

// ---------------------------------------------------------------------------
// final: out[g][o] = pooled_sum/count + bl  (binary-search counts)
// ---------------------------------------------------------------------------
__global__ void k_final(const float* __restrict__ bl, float* __restrict__ out,
                        int n, int G)
{
    int idx = blockIdx.x * blockDim.x + threadIdx.x;
    if (idx >= G * 2) return;
    int g = idx >> 1;
    int o = idx & 1;

    int lo = 0, hi = n;
    while (lo < hi) {
        int mid = (lo + hi) >> 1;
        if (g_batch[mid] < g) lo = mid + 1; else hi = mid;
    }
    int s = lo;
    lo = 0; hi = n;
    while (lo < hi) {
        int mid = (lo + hi) >> 1;
        if (g_batch[mid] < g + 1) lo = mid + 1; else hi = mid;
    }
    int t = lo;

    float sum = (float)(long long)g_pool[g * 2 + o] * POOL_INV;
    out[idx] = sum / fmaxf((float)(t - s), 1.0f) + bl[o];
}

// ---------------------------------------------------------------------------
static inline int ceil_div_i(int a, int b) { return (a + b - 1) / b; }

extern "C" void kernel_launch(void* const* d_in, const int* in_sizes, int n_in,
                              void* d_out, int out_size)
{
    (void)n_in;
    const float* x  = (const float*)d_in[0];
    const void*  ei = d_in[1];
    const float* ew = (const float*)d_in[2];
    const void*  bt = d_in[3];
    const float* W1 = (const float*)d_in[4];
    const float* b1 = (const float*)d_in[5];
    const float* W2 = (const float*)d_in[6];
    const float* b2 = (const float*)d_in[7];
    const float* Wl = (const float*)d_in[8];
    const float* bl = (const float*)d_in[9];
    float* out = (float*)d_out;

    int n = in_sizes[0] / HD;
    int e = in_sizes[2];
    int G = out_size / 2;

    int eb = ceil_div_i(e, 256);
    int nb = ceil_div_i(n, 1024);
    int gemm_blocks = ceil_div_i(n, 128);
    int agg_blocks  = ceil_div_i(n, 8);

    int gemm_smem = 4 * 128 * WPAD * (int)sizeof(__nv_bfloat16);  // 139264
    cudaFuncSetAttribute(k_gemm_tc, cudaFuncAttributeMaxDynamicSharedMemorySize,
                         gemm_smem);

    // fork side stream: wsplit + GEMM1 overlap the CSR build chain
    cudaStream_t s2 = 0;
    cudaEvent_t evA = 0, evB = 0;
    bool forked = false;
    if (cudaStreamCreateWithFlags(&s2, cudaStreamNonBlocking) == cudaSuccess &&
        cudaEventCreateWithFlags(&evA, cudaEventDisableTiming) == cudaSuccess &&
        cudaEventCreateWithFlags(&evB, cudaEventDisableTiming) == cudaSuccess) {
        if (cudaEventRecord(evA, 0) == cudaSuccess &&
            cudaStreamWaitEvent(s2, evA, 0) == cudaSuccess)
            forked = true;
    }

    cudaStream_t gs = forked ? s2 : (cudaStream_t)0;
    k_wsplit<<<ceil_div_i(HD * HD, 256), 256, 0, gs>>>(W1, W2);
    k_gemm_tc<<<gemm_blocks, 256, gemm_smem, gs>>>(x, 0, 0, n);
    if (forked) cudaEventRecord(evB, gs);

    // CSR build chain on main stream (g_degcnt pre-zeroed; prep1 clears
    // lookback flags and pooled-logit accumulators)
    k_prep1<<<eb, 256>>>(ei, bt, ew, n, e);
    k_scan_all<<<nb, 1024>>>(n, e);
    k_scatter<<<eb, 256>>>(ew, e);

    if (forked) cudaStreamWaitEvent(0, evB, 0);

    // agg1 -> GEMM2 -> agg2(+projection into pooled logits)
    k_agg<<<agg_blocks, 256>>>(b1, Wl, 0, n);                 // g_xwh  -> g_hh
    k_gemm_tc<<<gemm_blocks, 256, gemm_smem>>>(x, 1, 1, n);   // g_hh  -> g_xwh2
    k_agg<<<agg_blocks, 256>>>(b2, Wl, 1, n);                 // g_xwh2 -> g_pool

    // finalize: mean + bias
    k_final<<<ceil_div_i(G * 2, 256), 256>>>(bl, out, n, G);
}

// round 15
// speedup vs baseline: 1.0633x; 1.0633x over previous
#include <cuda_runtime.h>
#include <cuda_bf16.h>
#include <cuda_fp16.h>
#include <stdint.h>

// GCN graph classifier: 2x (GCNConv + ReLU) -> global_mean_pool -> Linear
// N=100k, E=1.6M, H=128, G=512, OUT=2.
//
// R15 = R13 (best, 249.0us) + deeper agg gather pipeline.
//  - R14's fused projection REVERTED: sorted batch => concurrent warps hit
//    the same g_pool address -> serialized L2 atomics (+14us). poolfinal is
//    back as a streaming pass.
//  - k_agg unrolled to 8 edges/iter: 8 edge-record loads + 8 gathers issued
//    before any consumption -> ~2x per-lane MLP on the latency-exposed path.
//  - retained from R13: packed 64-bit degree atomics, single-pass lookback
//    scan, split-bf16 TC GEMMs, fp16 intermediates, CSR || GEMM1 fork.

#define HD   128
#define NMAX 100352
#define EMAX 1605632
#define WPAD 136          // padded k-stride (bf16 elems) for smem tiles

__device__ __align__(16) unsigned long long g_degcnt[NMAX]; // zero-init; reset by scan
__device__ __align__(16) float g_dis[NMAX];
__device__ __align__(16) int   g_row[EMAX];
__device__ __align__(16) int   g_col[EMAX];
__device__ __align__(16) int   g_batch[NMAX];
__device__ __align__(16) int   g_off[NMAX + 1];
__device__ __align__(16) int   g_cur[NMAX];
__device__ __align__(16) int   g_bsum[128];          // lookback aggregates+flag
__device__ __align__(16) int2  g_edge[EMAX];         // {src row, coef bits}
__device__ __align__(16) __half g_xwh[(size_t)NMAX * HD];  // GEMM1 out (fp16)
__device__ __align__(16) __half g_xwh2[(size_t)NMAX * HD]; // GEMM2 out (fp16)
__device__ __align__(16) __half g_hh[(size_t)NMAX * HD];   // agg out (fp16)
__device__ __align__(16) __nv_bfloat16 g_Wh[2][HD * HD];   // W^T hi, [n][k]
__device__ __align__(16) __nv_bfloat16 g_Wl[2][HD * HD];   // W^T lo

// ---------------------------------------------------------------------------
// dtype detection (int64 arrays have zero hi-words at odd 32-bit indices)
// ---------------------------------------------------------------------------
__device__ __forceinline__ int detect_ei64(const int* ei32)
{
    int lane = threadIdx.x & 31;
    int v = ei32[2 * lane + 1];
    return __all_sync(0xffffffffu, v == 0);
}

__device__ __forceinline__ int detect_b64(const int* b32, int n)
{
    int lane = threadIdx.x & 31;
    int base = (n > 64) ? ((n - 64) & ~1) : 0;
    int v = b32[base + 2 * lane + 1];
    return __all_sync(0xffffffffu, v == 0);
}

// ---------------------------------------------------------------------------
// prep1: convert edge_index + batch; ONE packed 64-bit atomic per edge
// (hi32 = count, lo32 = ew * 2^24 fixed point). block 0 clears lookback flags.
// ---------------------------------------------------------------------------
__global__ void k_prep1(const void* __restrict__ ei, const void* __restrict__ bt,
                        const float* __restrict__ ew, int n, int e)
{
    __shared__ int s_ei64, s_b64;
    const int* ei32 = (const int*)ei;
    const int* bt32 = (const int*)bt;
    int tid = threadIdx.x;
    if (tid < 32) {
        int r = detect_ei64(ei32);
        if (tid == 0) s_ei64 = r;
    } else if (tid < 64) {
        int r = detect_b64(bt32, n);
        if (tid == 32) s_b64 = r;
    }
    if (blockIdx.x == 0 && tid < 128)
        g_bsum[tid] = 0;                 // clear lookback flags
    __syncthreads();

    int i = blockIdx.x * blockDim.x + tid;
    if (i < e) {
        int r, c;
        if (s_ei64) {
            const long long* p = (const long long*)ei;
            r = (int)p[i];
            c = (int)p[(size_t)e + i];
        } else {
            r = ei32[i];
            c = ei32[e + i];
        }
        g_row[i] = r;
        g_col[i] = c;
        unsigned fx = __float2uint_rn(ew[i] * 16777216.0f);   // ew * 2^24
        atomicAdd(&g_degcnt[c], (1ULL << 32) | (unsigned long long)fx);
    }
    if (i < n)
        g_batch[i] = s_b64 ? (int)((const long long*)bt)[i] : bt32[i];
}

// ---------------------------------------------------------------------------
// fused single-pass scan (decoupled lookback) + dis; resets g_degcnt.
// 98 blocks, all co-resident -> polling cannot deadlock.
// ---------------------------------------------------------------------------
__global__ void k_scan_all(int n, int e)
{
    __shared__ int s[1024];
    __shared__ int sbase;
    int b = blockIdx.x;
    int tid = threadIdx.x;
    int i = b * 1024 + tid;

    unsigned long long packed = 0;
    if (i < n) packed = g_degcnt[i];
    int v0 = (int)(packed >> 32);
    if (i < n) {
        float deg = (float)(unsigned)(packed & 0xffffffffu) * (1.0f / 16777216.0f);
        g_dis[i] = rsqrtf(deg + 1.0f);   // +1 = self-loop
        g_degcnt[i] = 0ULL;              // reset for next invocation
    }

    s[tid] = v0;
    __syncthreads();
    for (int off = 1; off < 1024; off <<= 1) {
        int t = 0;
        if (tid >= off) t = s[tid - off];
        __syncthreads();
        if (tid >= off) s[tid] += t;
        __syncthreads();
    }
    if (tid == 0) {
        sbase = 0;
        atomicExch(&g_bsum[b], (int)(0x80000000u | (unsigned)s[1023]));
    }
    __syncthreads();
    if (tid < b) {
        unsigned v;
        do {
            v = (unsigned)atomicAdd(&g_bsum[tid], 0);
        } while (!(v & 0x80000000u));
        atomicAdd(&sbase, (int)(v & 0x7fffffffu));
    }
    __syncthreads();
    if (i < n) {
        int ex = sbase + s[tid] - v0;   // exclusive prefix
        g_off[i] = ex;
        g_cur[i] = ex;
    }
    if (b == 0 && tid == 0) g_off[n] = e;
}

__global__ void k_scatter(const float* __restrict__ ew, int e)
{
    int i = blockIdx.x * blockDim.x + threadIdx.x;
    if (i >= e) return;
    int r = g_row[i];
    int c = g_col[i];
    float coef = g_dis[r] * ew[i] * g_dis[c];
    int slot = atomicAdd(&g_cur[c], 1);
    g_edge[slot] = make_int2(r, __float_as_int(coef));
}

// ---------------------------------------------------------------------------
// W split: W[k][n] fp32 -> transposed bf16 hi/lo [n][k]
// ---------------------------------------------------------------------------
__global__ void k_wsplit(const float* __restrict__ W1, const float* __restrict__ W2)
{
    int idx = blockIdx.x * blockDim.x + threadIdx.x;
    if (idx >= HD * HD) return;
    int k = idx >> 7, nn = idx & 127;
    float w1 = W1[idx], w2 = W2[idx];
    __nv_bfloat16 h1 = __float2bfloat16(w1);
    __nv_bfloat16 h2 = __float2bfloat16(w2);
    int o = nn * HD + k;
    g_Wh[0][o] = h1;
    g_Wl[0][o] = __float2bfloat16(w1 - __bfloat162float(h1));
    g_Wh[1][o] = h2;
    g_Wl[1][o] = __float2bfloat16(w2 - __bfloat162float(h2));
}

// ---------------------------------------------------------------------------
// tensor-core GEMM: Cout[rows x 128] = A[rows x 128] @ W  (split-bf16)
// A = Xin (fp32) when useH=0, g_hh (fp16) when useH=1.
// Cout: g_xwh (useH=0) or g_xwh2 (useH=1).
// ---------------------------------------------------------------------------
#define MMA16816(d, a, b)                                                     \
    asm volatile("mma.sync.aligned.m16n8k16.row.col.f32.bf16.bf16.f32 "       \
                 "{%0,%1,%2,%3}, {%4,%5,%6,%7}, {%8,%9}, {%0,%1,%2,%3};"      \
                 : "+f"((d)[0]), "+f"((d)[1]), "+f"((d)[2]), "+f"((d)[3])     \
                 : "r"((a)[0]), "r"((a)[1]), "r"((a)[2]), "r"((a)[3]),        \
                   "r"((b)[0]), "r"((b)[1]))

__global__ void __launch_bounds__(256) k_gemm_tc(const float* __restrict__ Xin,
                                                 int widx, int useH, int n)
{
    extern __shared__ __align__(16) char smraw[];
    __nv_bfloat16* Ah = (__nv_bfloat16*)smraw;       // [128][WPAD]
    __nv_bfloat16* Al = Ah + 128 * WPAD;
    __nv_bfloat16* Bh = Al + 128 * WPAD;             // W^T [n][k], [128][WPAD]
    __nv_bfloat16* Bl = Bh + 128 * WPAD;

    __half* Cout = useH ? g_xwh2 : g_xwh;
    int tid = threadIdx.x;
    int rowBase = blockIdx.x * 128;

    // stage + split A tile
#pragma unroll
    for (int i = 0; i < 16; i++) {
        int f4 = tid + i * 256;
        int r = f4 >> 5;
        int c4 = (f4 & 31) * 4;
        int ar = min(rowBase + r, n - 1);
        float4 v;
        if (useH) {
            uint2 hv = *(const uint2*)(g_hh + (size_t)ar * HD + c4);
            float2 f01 = __half22float2(*(__half2*)&hv.x);
            float2 f23 = __half22float2(*(__half2*)&hv.y);
            v = make_float4(f01.x, f01.y, f23.x, f23.y);
        } else {
            v = *(const float4*)(Xin + (size_t)ar * HD + c4);
        }
        __nv_bfloat16 hx = __float2bfloat16(v.x);
        __nv_bfloat16 hy = __float2bfloat16(v.y);
        __nv_bfloat16 hz = __float2bfloat16(v.z);
        __nv_bfloat16 hw = __float2bfloat16(v.w);
        __nv_bfloat16 lx = __float2bfloat16(v.x - __bfloat162float(hx));
        __nv_bfloat16 ly = __float2bfloat16(v.y - __bfloat162float(hy));
        __nv_bfloat16 lz = __float2bfloat16(v.z - __bfloat162float(hz));
        __nv_bfloat16 lw = __float2bfloat16(v.w - __bfloat162float(hw));
        __nv_bfloat162 h01, h23, l01, l23;
        h01.x = hx; h01.y = hy; h23.x = hz; h23.y = hw;
        l01.x = lx; l01.y = ly; l23.x = lz; l23.y = lw;
        uint2 uh, ul;
        uh.x = *(uint32_t*)&h01; uh.y = *(uint32_t*)&h23;
        ul.x = *(uint32_t*)&l01; ul.y = *(uint32_t*)&l23;
        *(uint2*)&Ah[r * WPAD + c4] = uh;
        *(uint2*)&Al[r * WPAD + c4] = ul;
    }

    // stage W^T tiles
#pragma unroll
    for (int i = 0; i < 8; i++) {
        int idx8 = (tid + i * 256) * 8;
        int r = idx8 >> 7;
        int c = idx8 & 127;
        *(uint4*)&Bh[r * WPAD + c] = *(const uint4*)&g_Wh[widx][idx8];
        *(uint4*)&Bl[r * WPAD + c] = *(const uint4*)&g_Wl[widx][idx8];
    }
    __syncthreads();

    int lane = tid & 31;
    int w = tid >> 5;
    int g = lane >> 2;
    int t = lane & 3;
    int wm0 = (w & 1) * 64;
    int wn0 = (w >> 1) * 32;

    float acc[4][4][4];
#pragma unroll
    for (int mb = 0; mb < 4; mb++)
#pragma unroll
        for (int nb = 0; nb < 4; nb++)
#pragma unroll
            for (int q = 0; q < 4; q++) acc[mb][nb][q] = 0.0f;

#pragma unroll
    for (int ks = 0; ks < 8; ks++) {
        int k0 = ks * 16 + t * 2;
        uint32_t ah[4][4], al[4][4];
#pragma unroll
        for (int mb = 0; mb < 4; mb++) {
            int r0 = wm0 + mb * 16 + g;
            ah[mb][0] = *(const uint32_t*)&Ah[r0 * WPAD + k0];
            ah[mb][1] = *(const uint32_t*)&Ah[(r0 + 8) * WPAD + k0];
            ah[mb][2] = *(const uint32_t*)&Ah[r0 * WPAD + k0 + 8];
            ah[mb][3] = *(const uint32_t*)&Ah[(r0 + 8) * WPAD + k0 + 8];
            al[mb][0] = *(const uint32_t*)&Al[r0 * WPAD + k0];
            al[mb][1] = *(const uint32_t*)&Al[(r0 + 8) * WPAD + k0];
            al[mb][2] = *(const uint32_t*)&Al[r0 * WPAD + k0 + 8];
            al[mb][3] = *(const uint32_t*)&Al[(r0 + 8) * WPAD + k0 + 8];
        }
        uint32_t bh[4][2], bl[4][2];
#pragma unroll
        for (int nb = 0; nb < 4; nb++) {
            int nr = wn0 + nb * 8 + g;
            bh[nb][0] = *(const uint32_t*)&Bh[nr * WPAD + k0];
            bh[nb][1] = *(const uint32_t*)&Bh[nr * WPAD + k0 + 8];
            bl[nb][0] = *(const uint32_t*)&Bl[nr * WPAD + k0];
            bl[nb][1] = *(const uint32_t*)&Bl[nr * WPAD + k0 + 8];
        }
#pragma unroll
        for (int mb = 0; mb < 4; mb++)
#pragma unroll
            for (int nb = 0; nb < 4; nb++) {
                MMA16816(acc[mb][nb], ah[mb], bh[nb]);
                MMA16816(acc[mb][nb], ah[mb], bl[nb]);
                MMA16816(acc[mb][nb], al[mb], bh[nb]);
            }
    }

    // write C as fp16
#pragma unroll
    for (int mb = 0; mb < 4; mb++) {
#pragma unroll
        for (int nb = 0; nb < 4; nb++) {
            int r0 = rowBase + wm0 + mb * 16 + g;
            int c0 = wn0 + nb * 8 + t * 2;
            if (r0 < n) {
                __half2 v0 = __floats2half2_rn(acc[mb][nb][0], acc[mb][nb][1]);
                *(__half2*)&Cout[(size_t)r0 * HD + c0] = v0;
            }
            if (r0 + 8 < n) {
                __half2 v1 = __floats2half2_rn(acc[mb][nb][2], acc[mb][nb][3]);
                *(__half2*)&Cout[(size_t)(r0 + 8) * HD + c0] = v1;
            }
        }
    }
}

// ---------------------------------------------------------------------------
// aggregation: fp16 gathers, fp32 accumulate, fp16 output to g_hh.
// warp per node, full grid. 8-deep gather pipeline for MLP.
// srcSel: 0 -> g_xwh, 1 -> g_xwh2.
// ---------------------------------------------------------------------------
__device__ __forceinline__ void h4_acc(float4& acc, uint2 u, float c)
{
    float2 f01 = __half22float2(*(__half2*)&u.x);
    float2 f23 = __half22float2(*(__half2*)&u.y);
    acc.x += c * f01.x;
    acc.y += c * f01.y;
    acc.z += c * f23.x;
    acc.w += c * f23.y;
}

__global__ void k_agg(const float* __restrict__ bias, int srcSel, int n)
{
    int gw = (blockIdx.x * blockDim.x + threadIdx.x) >> 5;
    int lane = threadIdx.x & 31;
    if (gw >= n) return;

    const uint2* x2 = (const uint2*)(srcSel ? g_xwh2 : g_xwh);
    float sc = g_dis[gw];
    float4 acc = make_float4(0.f, 0.f, 0.f, 0.f);
    h4_acc(acc, x2[(size_t)gw * 32 + lane], sc * sc);

    int p  = g_off[gw];
    int p1 = g_off[gw + 1];
    // 8-deep: batch all edge-record loads, then all gathers, then consume
    for (; p + 7 < p1; p += 8) {
        int2 er[8];
#pragma unroll
        for (int j = 0; j < 8; j++) er[j] = g_edge[p + j];
        uint2 u[8];
#pragma unroll
        for (int j = 0; j < 8; j++)
            u[j] = x2[(size_t)er[j].x * 32 + lane];
#pragma unroll
        for (int j = 0; j < 8; j++)
            h4_acc(acc, u[j], __int_as_float(er[j].y));
    }
    for (; p + 1 < p1; p += 2) {
        int2 e0 = g_edge[p];
        int2 e1 = g_edge[p + 1];
        uint2 u0 = x2[(size_t)e0.x * 32 + lane];
        uint2 u1 = x2[(size_t)e1.x * 32 + lane];
        h4_acc(acc, u0, __int_as_float(e0.y));
        h4_acc(acc, u1, __int_as_float(e1.y));
    }
    if (p < p1) {
        int2 e0 = g_edge[p];
        uint2 u0 = x2[(size_t)e0.x * 32 + lane];
        h4_acc(acc, u0, __int_as_float(e0.y));
    }

    float4 bb = ((const float4*)bias)[lane];
    __half2 h01 = __floats2half2_rn(fmaxf(acc.x + bb.x, 0.0f),
                                    fmaxf(acc.y + bb.y, 0.0f));
    __half2 h23 = __floats2half2_rn(fmaxf(acc.z + bb.z, 0.0f),
                                    fmaxf(acc.w + bb.w, 0.0f));
    uint2 u;
    u.x = *(uint32_t*)&h01;
    u.y = *(uint32_t*)&h23;
    *(uint2*)&g_hh[(size_t)gw * HD + 4 * lane] = u;
}

// ---------------------------------------------------------------------------
// pooling + classifier over fp16 g_hh (binary-search graph bounds)
// ---------------------------------------------------------------------------
__global__ void k_poolfinal(const float* __restrict__ Wl, const float* __restrict__ bl,
                            float* __restrict__ out, int n)
{
    int g = blockIdx.x;
    int f = threadIdx.x;
    __shared__ int sb[2];
    __shared__ float r0[128], r1[128];

    if (f < 2) {
        int target = g + f;
        int lo = 0, hi = n;
        while (lo < hi) {
            int mid = (lo + hi) >> 1;
            if (g_batch[mid] < target) lo = mid + 1; else hi = mid;
        }
        sb[f] = lo;
    }
    __syncthreads();
    int s = sb[0], t = sb[1];

    float acc = 0.0f;
    for (int i = s; i < t; i++)
        acc += __half2float(g_hh[(size_t)i * HD + f]);
    float pooled = acc / fmaxf((float)(t - s), 1.0f);

    r0[f] = pooled * Wl[f * 2 + 0];
    r1[f] = pooled * Wl[f * 2 + 1];
    __syncthreads();
#pragma unroll
    for (int off = 64; off > 0; off >>= 1) {
        if (f < off) { r0[f] += r0[f + off]; r1[f] += r1[f + off]; }
        __syncthreads();
    }
    if (f == 0) {
        out[g * 2 + 0] = r0[0] + bl[0];
        out[g * 2 + 1] = r1[0] + bl[1];
    }
}

// ---------------------------------------------------------------------------
static inline int ceil_div_i(int a, int b) { return (a + b - 1) / b; }

extern "C" void kernel_launch(void* const* d_in, const int* in_sizes, int n_in,
                              void* d_out, int out_size)
{
    (void)n_in;
    const float* x  = (const float*)d_in[0];
    const void*  ei = d_in[1];
    const float* ew = (const float*)d_in[2];
    const void*  bt = d_in[3];
    const float* W1 = (const float*)d_in[4];
    const float* b1 = (const float*)d_in[5];
    const float* W2 = (const float*)d_in[6];
    const float* b2 = (const float*)d_in[7];
    const float* Wl = (const float*)d_in[8];
    const float* bl = (const float*)d_in[9];
    float* out = (float*)d_out;

    int n = in_sizes[0] / HD;
    int e = in_sizes[2];
    int G = out_size / 2;

    int eb = ceil_div_i(e, 256);
    int nb = ceil_div_i(n, 1024);
    int gemm_blocks = ceil_div_i(n, 128);
    int agg_blocks  = ceil_div_i(n, 8);

    int gemm_smem = 4 * 128 * WPAD * (int)sizeof(__nv_bfloat16);  // 139264
    cudaFuncSetAttribute(k_gemm_tc, cudaFuncAttributeMaxDynamicSharedMemorySize,
                         gemm_smem);

    // fork side stream: wsplit + GEMM1 overlap the CSR build chain
    cudaStream_t s2 = 0;
    cudaEvent_t evA = 0, evB = 0;
    bool forked = false;
    if (cudaStreamCreateWithFlags(&s2, cudaStreamNonBlocking) == cudaSuccess &&
        cudaEventCreateWithFlags(&evA, cudaEventDisableTiming) == cudaSuccess &&
        cudaEventCreateWithFlags(&evB, cudaEventDisableTiming) == cudaSuccess) {
        if (cudaEventRecord(evA, 0) == cudaSuccess &&
            cudaStreamWaitEvent(s2, evA, 0) == cudaSuccess)
            forked = true;
    }

    cudaStream_t gs = forked ? s2 : (cudaStream_t)0;
    k_wsplit<<<ceil_div_i(HD * HD, 256), 256, 0, gs>>>(W1, W2);
    k_gemm_tc<<<gemm_blocks, 256, gemm_smem, gs>>>(x, 0, 0, n);
    if (forked) cudaEventRecord(evB, gs);

    // CSR build chain on main stream (g_degcnt pre-zeroed; prep1 clears flags)
    k_prep1<<<eb, 256>>>(ei, bt, ew, n, e);
    k_scan_all<<<nb, 1024>>>(n, e);
    k_scatter<<<eb, 256>>>(ew, e);

    if (forked) cudaStreamWaitEvent(0, evB, 0);

    // layer 1 aggregate -> layer 2 GEMM -> layer 2 aggregate (full grids)
    k_agg<<<agg_blocks, 256>>>(b1, 0, n);                     // g_xwh  -> g_hh
    k_gemm_tc<<<gemm_blocks, 256, gemm_smem>>>(x, 1, 1, n);   // g_hh  -> g_xwh2
    k_agg<<<agg_blocks, 256>>>(b2, 1, n);                     // g_xwh2 -> g_hh

    // pooling + classifier
    k_poolfinal<<<G, 128>>>(Wl, bl, out, n);
}